// round 3
// baseline (speedup 1.0000x reference)
#include <cuda_runtime.h>
#include <math.h>

typedef unsigned long long ull;

#define NDIM 512
#define DDIM 784
#define CDIM 10
#define ITERS 40
#define QMAX 127.0f

#define CLUSTER 8
#define GRID 128
#define TPB 256
#define WSTRIDE 68          // padded floats per k-row of sWt (272B, 16B-aligned)

// shared layout (float offsets)
#define S_WT   0            // 512*68 = 34816
#define S_Z    34816        // 2 buffers x 4096
#define S_RED  43008        // 8*512 = 4096
#define S_UX   47104        // 512
#define S_SCR  47616        // 64
#define SMEM_FLOATS 47680
#define SMEM_BYTES (SMEM_FLOATS*4)
#define ZBYTE (S_Z*4)

// ---------------- PTX helpers ----------------
__device__ __forceinline__ unsigned smem_u32(const void* p){
    unsigned r; asm("{.reg .u64 t; cvta.to.shared.u64 t, %1; cvt.u32.u64 %0, t;}" : "=r"(r) : "l"(p)); return r;
}
__device__ __forceinline__ unsigned mapa8(unsigned a, unsigned r){
    unsigned d; asm("mapa.shared::cluster.u32 %0, %1, %2;" : "=r"(d) : "r"(a), "r"(r)); return d;
}
__device__ __forceinline__ void stc64(unsigned a, ull v){
    asm volatile("st.shared::cluster.b64 [%0], %1;" :: "r"(a), "l"(v) : "memory");
}
__device__ __forceinline__ float ldc32(unsigned a){
    float v; asm volatile("ld.shared::cluster.b32 %0, [%1];" : "=f"(v) : "r"(a)); return v;
}
#define CLUSTER_SYNC_() do{ \
    asm volatile("barrier.cluster.arrive.aligned;" ::: "memory"); \
    asm volatile("barrier.cluster.wait.aligned;"   ::: "memory"); }while(0)

__device__ __forceinline__ ull pk2(float x){
    ull d; asm("mov.b64 %0, {%1,%1};" : "=l"(d) : "r"(__float_as_uint(x))); return d;
}
__device__ __forceinline__ ull pk2b(float x, float y){
    ull d; asm("mov.b64 %0, {%1,%2};" : "=l"(d) : "r"(__float_as_uint(x)), "r"(__float_as_uint(y))); return d;
}
__device__ __forceinline__ void upk2(ull v, float& x, float& y){
    unsigned a, b; asm("mov.b64 {%0,%1}, %2;" : "=r"(a), "=r"(b) : "l"(v));
    x = __uint_as_float(a); y = __uint_as_float(b);
}
__device__ __forceinline__ void fma2(ull& d, ull a, ull b){
    asm("fma.rn.f32x2 %0, %1, %2, %3;" : "=l"(d) : "l"(a), "l"(b), "l"(d));
}
__device__ __forceinline__ ull add2(ull a, ull b){
    ull d; asm("add.rn.f32x2 %0, %1, %2;" : "=l"(d) : "l"(a), "l"(b)); return d;
}
__device__ __forceinline__ ull mul2(ull a, ull b){
    ull d; asm("mul.rn.f32x2 %0, %1, %2;" : "=l"(d) : "l"(a), "l"(b)); return d;
}
__device__ __forceinline__ float warpmax(float v){
    #pragma unroll
    for (int o = 16; o; o >>= 1) v = fmaxf(v, __shfl_xor_sync(0xffffffffu, v, o));
    return v;
}

extern "C" __global__ void __launch_bounds__(TPB, 1) __cluster_dims__(CLUSTER, 1, 1)
mondeq_kernel(const float* __restrict__ W, const float* __restrict__ U,
              const float* __restrict__ bvec, const float* __restrict__ x,
              const float* __restrict__ Wc, const float* __restrict__ bcv,
              float* __restrict__ out)
{
    extern __shared__ float sm[];
    float* sWt  = sm + S_WT;
    float* sZ   = sm + S_Z;
    float* sRed = sm + S_RED;
    float* sUx  = sm + S_UX;
    float* scr  = sm + S_SCR;

    const int tid = threadIdx.x;
    unsigned mi_u; asm("mov.u32 %0, %%cluster_ctarank;" : "=r"(mi_u));
    const int mi = (int)mi_u;                 // row tile 0..7 (64 rows each)
    const int nj = blockIdx.x >> 3;           // column group 0..15 (8 batch cols)

    const unsigned mybase = smem_u32(sm);
    unsigned pbase[CLUSTER];
    #pragma unroll
    for (int r = 0; r < CLUSTER; ++r) pbase[r] = mapa8(mybase, (unsigned)r);

    // ================= Phase A: per-tensor max|.| (cluster-local) =================
    {
        float lw = 0.f, lu = 0.f, lb = 0.f;
        const float4* W4 = (const float4*)(W + (size_t)(mi*64)*NDIM);
        for (int i = tid; i < 64*NDIM/4; i += TPB) {
            float4 v = W4[i];
            lw = fmaxf(lw, fmaxf(fmaxf(fabsf(v.x),fabsf(v.y)), fmaxf(fabsf(v.z),fabsf(v.w))));
        }
        const float4* U4 = (const float4*)(U + (size_t)(mi*64)*DDIM);
        for (int i = tid; i < 64*DDIM/4; i += TPB) {
            float4 v = U4[i];
            lu = fmaxf(lu, fmaxf(fmaxf(fabsf(v.x),fabsf(v.y)), fmaxf(fabsf(v.z),fabsf(v.w))));
        }
        if (tid < 64) lb = fabsf(bvec[mi*64 + tid]);
        lw = warpmax(lw); lu = warpmax(lu); lb = warpmax(lb);
        const int wid = tid >> 5, lane = tid & 31;
        if (lane == 0) { sRed[wid] = lw; sRed[8+wid] = lu; sRed[16+wid] = lb; }
        __syncthreads();
        if (tid == 0) {
            float mw=0.f, mu=0.f, mb=0.f;
            #pragma unroll
            for (int i = 0; i < 8; ++i) {
                mw = fmaxf(mw, sRed[i]); mu = fmaxf(mu, sRed[8+i]); mb = fmaxf(mb, sRed[16+i]);
            }
            scr[0] = mw; scr[1] = mu; scr[2] = mb;
        }
    }
    CLUSTER_SYNC_();
    if (tid < CLUSTER) {
        unsigned pa = mapa8(mybase + S_SCR*4, (unsigned)tid);
        scr[8  + tid] = ldc32(pa);
        scr[16 + tid] = ldc32(pa + 4);
        scr[24 + tid] = ldc32(pa + 8);
    }
    __syncthreads();
    float mw = 0.f, mu = 0.f, mb = 0.f;
    #pragma unroll
    for (int r = 0; r < CLUSTER; ++r) {
        mw = fmaxf(mw, scr[8+r]); mu = fmaxf(mu, scr[16+r]); mb = fmaxf(mb, scr[24+r]);
    }
    const float scW = mw / QMAX, scU = mu / QMAX, scB = mb / QMAX;

    // ================= Phase B: Ux tile + z1 (xs staged in sWt region) =============
    {
        // xs[k][8] for this group's 8 batch columns
        #pragma unroll
        for (int bl = 0; bl < 8; ++bl) {
            const float* xr = x + (size_t)(nj*8 + bl)*DDIM;
            for (int k = tid; k < DDIM; k += TPB) sWt[k*8 + bl] = xr[k];
        }
        __syncthreads();

        const int r = tid >> 2, ks = tid & 3, k0 = ks*196;
        ull a0=0, a1=0, a2=0, a3=0;
        const float* up = U + (size_t)(mi*64 + r)*DDIM + k0;
        const float* xp = sWt + (size_t)k0*8;
        #pragma unroll 2
        for (int j = 0; j < 196; j += 4) {
            float4 u4 = *(const float4*)(up + j);
            float q[4];
            q[0] = rintf(u4.x/scU)*scU; q[1] = rintf(u4.y/scU)*scU;
            q[2] = rintf(u4.z/scU)*scU; q[3] = rintf(u4.w/scU)*scU;
            #pragma unroll
            for (int e = 0; e < 4; ++e) {
                ulonglong2 xa = *(const ulonglong2*)(xp + (j+e)*8);
                ulonglong2 xb = *(const ulonglong2*)(xp + (j+e)*8 + 4);
                ull qp = pk2(q[e]);
                fma2(a0, qp, xa.x); fma2(a1, qp, xa.y);
                fma2(a2, qp, xb.x); fma2(a3, qp, xb.y);
            }
        }
        ull* rp = (ull*)(sRed + ks*512 + r*8);
        rp[0] = a0; rp[1] = a1; rp[2] = a2; rp[3] = a3;
        __syncthreads();

        const int row = tid >> 2, cp = (tid & 3) << 1, o = row*8 + cp;
        ull s = *(const ull*)(sRed + o);
        #pragma unroll
        for (int q = 1; q < 4; ++q) s = add2(s, *(const ull*)(sRed + q*512 + o));
        const float bq = rintf(bvec[mi*64 + row]/scB)*scB;
        s = add2(s, pk2(bq));
        *(ull*)(sUx + o) = s;
        float f0, f1; upk2(s, f0, f1);
        ull z1 = pk2b(fmaxf(0.5f*f0, 0.f), fmaxf(0.5f*f1, 0.f));
        const unsigned zoff = ZBYTE + 16384u + (unsigned)(((mi*64 + row)*8 + cp)*4); // buf1
        #pragma unroll
        for (int r2 = 0; r2 < CLUSTER; ++r2) stc64(pbase[r2] + zoff, z1);
        __syncthreads();   // xs reads done before sWt overwrite
    }

    // ================= Phase C: quantized W tile -> SMEM (transposed) ==============
    for (int i = tid; i < 64*NDIM; i += TPB) {
        const int nl = i >> 9, k = i & 511;
        sWt[k*WSTRIDE + nl] = rintf(W[(size_t)(mi*64 + nl)*NDIM + k]/scW)*scW;
    }
    CLUSTER_SYNC_();   // publish z1 + W tile ready (block barrier included)

    // ================= Main loop: 39 iterations ====================================
    const int wid  = tid >> 5;              // K-split 0..7 (64 k each)
    const int lane = tid & 31;
    const int nb   = (lane >> 2) << 3;      // 8-row group: 0,8,...,56
    const int bp   = (lane & 3) << 1;       // col pair: 0,2,4,6
    const float* sWb = sWt + wid*64*WSTRIDE + nb;
    const int row  = tid >> 2;              // combine-phase mapping
    const int cp   = (tid & 3) << 1;
    const int oidx = row*8 + cp;
    const int gz   = (mi*64 + row)*8 + cp;
    const ull H05  = pk2(0.5f);

    int rb = 1;
    for (int it = 1; it < ITERS; ++it) {
        const float* zr = sZ + rb*4096 + wid*512 + bp;
        ull a0=0,a1=0,a2=0,a3=0,a4=0,a5=0,a6=0,a7=0;
        #pragma unroll 8
        for (int k = 0; k < 64; ++k) {
            ulonglong2 wa = *(const ulonglong2*)(sWb + k*WSTRIDE);
            ulonglong2 wb = *(const ulonglong2*)(sWb + k*WSTRIDE + 4);
            float2 zz = *(const float2*)(zr + k*8);
            ull z0 = pk2(zz.x), z1 = pk2(zz.y);
            fma2(a0, wa.x, z0); fma2(a1, wa.x, z1);
            fma2(a2, wa.y, z0); fma2(a3, wa.y, z1);
            fma2(a4, wb.x, z0); fma2(a5, wb.x, z1);
            fma2(a6, wb.y, z0); fma2(a7, wb.y, z1);
        }
        {
            float* rp = sRed + wid*512 + nb*8 + bp;
            float x0, x1;
            upk2(a0,x0,x1); rp[0]  = x0; rp[8]  = x1;
            upk2(a1,x0,x1); rp[1]  = x0; rp[9]  = x1;
            upk2(a2,x0,x1); rp[16] = x0; rp[24] = x1;
            upk2(a3,x0,x1); rp[17] = x0; rp[25] = x1;
            upk2(a4,x0,x1); rp[32] = x0; rp[40] = x1;
            upk2(a5,x0,x1); rp[33] = x0; rp[41] = x1;
            upk2(a6,x0,x1); rp[48] = x0; rp[56] = x1;
            upk2(a7,x0,x1); rp[49] = x0; rp[57] = x1;
        }
        __syncthreads();
        {
            const float* rq = sRed + oidx;
            ull s = *(const ull*)(rq);
            #pragma unroll
            for (int q = 1; q < 8; ++q) s = add2(s, *(const ull*)(rq + q*512));
            ull uxv = *(const ull*)(sUx + oidx);
            ull zov = *(const ull*)(sZ + rb*4096 + gz);
            ull v = mul2(add2(add2(s, uxv), zov), H05);   // 0.5*(z + (Wz+Ux)) == 0.5z+0.5(Wz+Ux)
            float f0, f1; upk2(v, f0, f1);
            ull zn = pk2b(fmaxf(f0, 0.f), fmaxf(f1, 0.f));
            const unsigned zoff = ZBYTE + (unsigned)((rb^1)*16384) + (unsigned)(gz*4);
            #pragma unroll
            for (int r2 = 0; r2 < CLUSTER; ++r2) stc64(pbase[r2] + zoff, zn);
        }
        CLUSTER_SYNC_();   // also acts as block barrier protecting sRed reuse
        rb ^= 1;
    }
    // final z (iter 40) is in buffer 0 on every CTA

    // ================= Classifier (CTA rank 0 of each cluster) ====================
    if (mi == 0 && tid < 8*CDIM) {
        const int bl = tid / CDIM, c = tid - bl*CDIM;
        const float* zp = sZ + bl;        // buf0, stride 8
        const float* wc = Wc + c*NDIM;
        float acc = bcv[c];
        #pragma unroll 8
        for (int n = 0; n < NDIM; ++n) acc = fmaf(zp[n*8], wc[n], acc);
        out[(nj*8 + bl)*CDIM + c] = acc;
    }
}

extern "C" void kernel_launch(void* const* d_in, const int* in_sizes, int n_in,
                              void* d_out, int out_size) {
    (void)in_sizes; (void)n_in; (void)out_size;
    cudaFuncSetAttribute(mondeq_kernel, cudaFuncAttributeMaxDynamicSharedMemorySize, SMEM_BYTES);
    mondeq_kernel<<<GRID, TPB, SMEM_BYTES>>>(
        (const float*)d_in[0],   // W  (512,512)
        (const float*)d_in[1],   // U  (512,784)
        (const float*)d_in[2],   // b  (512)
        (const float*)d_in[3],   // x  (128,784)
        (const float*)d_in[4],   // Wc (10,512)
        (const float*)d_in[5],   // bc (10)
        (float*)d_out);          // logits (128,10)
}

// round 4
// speedup vs baseline: 1.4913x; 1.4913x over previous
#include <cuda_runtime.h>
#include <math.h>

typedef unsigned long long ull;

#define NDIM 512
#define DDIM 784
#define CDIM 10
#define ITERS 40
#define QMAX 127.0f

#define MT 8          // row tiles (64 rows each)
#define NT 16         // column groups (8 cols each)
#define GRID (MT*NT)  // 128 CTAs
#define TPB 256
#define WSTRIDE 68    // padded floats per k-row of sWt (272B, 16B aligned)

// shared layout (float offsets)
#define S_WT   0          // 512*68 = 34816
#define S_Z    34816      // 2 x 4096 (double-buffered staged z)
#define S_RED  43008      // 8*512
#define S_UX   47104      // 512
#define SMEM_FLOATS 47616
#define SMEM_BYTES (SMEM_FLOATS*4)

// ---- device globals (scratch) ----
__device__ float g_Ux[NDIM*128];
__device__ float g_zA[NDIM*128];
__device__ float g_zB[NDIM*128];
__device__ unsigned g_maxW, g_maxU, g_maxB;
__device__ unsigned g_gcnt, g_ggen;          // full-grid barrier
__device__ unsigned g_cnt[NT], g_gen[NT];    // per-group barriers

// -------- release/acquire barrier (no membar, no nanosleep) --------
__device__ __forceinline__ void gbar(unsigned* cnt, unsigned* gen, unsigned expected) {
    __syncthreads();
    if (threadIdx.x == 0) {
        unsigned snap, t;
        asm volatile("ld.acquire.gpu.global.u32 %0, [%1];" : "=r"(snap) : "l"(gen) : "memory");
        asm volatile("atom.acq_rel.gpu.global.add.u32 %0, [%1], %2;"
                     : "=r"(t) : "l"(cnt), "r"(1u) : "memory");
        if (t == expected - 1u) {
            asm volatile("st.relaxed.gpu.global.u32 [%0], %1;" :: "l"(cnt), "r"(0u) : "memory");
            asm volatile("red.release.gpu.global.add.u32 [%0], %1;" :: "l"(gen), "r"(1u) : "memory");
        } else {
            unsigned g;
            do {
                asm volatile("ld.acquire.gpu.global.u32 %0, [%1];" : "=r"(g) : "l"(gen) : "memory");
            } while (g == snap);
        }
    }
    __syncthreads();
}

// -------- f32x2 helpers --------
__device__ __forceinline__ ull pk2(float x){
    ull d; asm("mov.b64 %0, {%1,%1};" : "=l"(d) : "r"(__float_as_uint(x))); return d;
}
__device__ __forceinline__ ull pk2b(float x, float y){
    ull d; asm("mov.b64 %0, {%1,%2};" : "=l"(d) : "r"(__float_as_uint(x)), "r"(__float_as_uint(y))); return d;
}
__device__ __forceinline__ void upk2(ull v, float& x, float& y){
    unsigned a, b; asm("mov.b64 {%0,%1}, %2;" : "=r"(a), "=r"(b) : "l"(v));
    x = __uint_as_float(a); y = __uint_as_float(b);
}
__device__ __forceinline__ void fma2(ull& d, ull a, ull b){
    asm("fma.rn.f32x2 %0, %1, %2, %3;" : "=l"(d) : "l"(a), "l"(b), "l"(d));
}
__device__ __forceinline__ ull add2(ull a, ull b){
    ull d; asm("add.rn.f32x2 %0, %1, %2;" : "=l"(d) : "l"(a), "l"(b)); return d;
}
__device__ __forceinline__ float warpmax(float v){
    #pragma unroll
    for (int o = 16; o; o >>= 1) v = fmaxf(v, __shfl_xor_sync(0xffffffffu, v, o));
    return v;
}

extern "C" __global__ void __launch_bounds__(TPB, 1)
mondeq_kernel(const float* __restrict__ W, const float* __restrict__ U,
              const float* __restrict__ bvec, const float* __restrict__ x,
              const float* __restrict__ Wc, const float* __restrict__ bcv,
              float* __restrict__ out)
{
    extern __shared__ float sm[];
    float* sWt  = sm + S_WT;
    float* sZ   = sm + S_Z;
    float* sRed = sm + S_RED;
    float* sUx  = sm + S_UX;

    const int tid = threadIdx.x;
    const int cta = blockIdx.x;
    const int mi  = cta & (MT - 1);   // row tile
    const int nj  = cta >> 3;         // column group

    // ================= Phase A: per-tensor max|.| =================
    {
        float lw = 0.f, lu = 0.f, lb = 0.f;
        const int gid = cta * TPB + tid;
        for (int i = gid; i < NDIM*NDIM; i += GRID*TPB) lw = fmaxf(lw, fabsf(W[i]));
        for (int i = gid; i < NDIM*DDIM; i += GRID*TPB) lu = fmaxf(lu, fabsf(U[i]));
        if (gid < NDIM) lb = fabsf(bvec[gid]);
        lw = warpmax(lw); lu = warpmax(lu); lb = warpmax(lb);
        const int wid = tid >> 5, lane = tid & 31;
        if (lane == 0) { sm[wid] = lw; sm[8 + wid] = lu; sm[16 + wid] = lb; }
        __syncthreads();
        if (tid == 0) {
            float mw = 0.f, mu = 0.f, mb = 0.f;
            #pragma unroll
            for (int i = 0; i < 8; ++i) {
                mw = fmaxf(mw, sm[i]); mu = fmaxf(mu, sm[8+i]); mb = fmaxf(mb, sm[16+i]);
            }
            atomicMax(&g_maxW, __float_as_uint(mw));
            atomicMax(&g_maxU, __float_as_uint(mu));
            atomicMax(&g_maxB, __float_as_uint(mb));
        }
    }
    gbar(&g_gcnt, &g_ggen, GRID);

    const float scW = __uint_as_float(__ldcg(&g_maxW)) / QMAX;
    const float scU = __uint_as_float(__ldcg(&g_maxU)) / QMAX;
    const float scB = __uint_as_float(__ldcg(&g_maxB)) / QMAX;

    // ================= Phase B: Ux = Uq @ x^T + bq  (4 rows per CTA) =================
    {
        float* xs = sm;            // 128 x 112, stride 113
        float* us = sm + 14464;    // 4 x 112 quantized U rows
        float* hb = sm + 14912;    // 512 half-combine scratch
        const int n0   = cta * 4;
        const int half = tid >> 7;
        const int bcol = tid & 127;
        float a0 = 0.f, a1 = 0.f, a2 = 0.f, a3 = 0.f;
        for (int ch = 0; ch < 7; ++ch) {
            const int k0 = ch * 112;
            __syncthreads();
            for (int i = tid; i < 128*112; i += TPB) {
                int bb = i / 112, kk = i - bb*112;
                xs[bb*113 + kk] = x[bb*DDIM + k0 + kk];
            }
            for (int i = tid; i < 4*112; i += TPB) {
                int rr = i / 112, kk = i - rr*112;
                us[rr*112 + kk] = rintf(U[(n0+rr)*DDIM + k0 + kk] / scU) * scU;
            }
            __syncthreads();
            if ((ch & 1) == half) {
                const float* xr = xs + bcol*113;
                #pragma unroll 4
                for (int kk = 0; kk < 112; ++kk) {
                    float xv = xr[kk];
                    a0 = fmaf(us[kk],       xv, a0);
                    a1 = fmaf(us[112 + kk], xv, a1);
                    a2 = fmaf(us[224 + kk], xv, a2);
                    a3 = fmaf(us[336 + kk], xv, a3);
                }
            }
        }
        __syncthreads();
        if (half == 1) {
            hb[bcol] = a0; hb[128+bcol] = a1; hb[256+bcol] = a2; hb[384+bcol] = a3;
        }
        __syncthreads();
        if (half == 0) {
            const float bq0 = rintf(bvec[n0+0] / scB) * scB;
            const float bq1 = rintf(bvec[n0+1] / scB) * scB;
            const float bq2 = rintf(bvec[n0+2] / scB) * scB;
            const float bq3 = rintf(bvec[n0+3] / scB) * scB;
            const int base = (bcol >> 3) * (NDIM*8) + (bcol & 7);
            __stcg(&g_Ux[base + (n0+0)*8], a0 + hb[bcol]       + bq0);
            __stcg(&g_Ux[base + (n0+1)*8], a1 + hb[128 + bcol] + bq1);
            __stcg(&g_Ux[base + (n0+2)*8], a2 + hb[256 + bcol] + bq2);
            __stcg(&g_Ux[base + (n0+3)*8], a3 + hb[384 + bcol] + bq3);
        }
        __syncthreads();   // xs reads done before sWt overwrite
    }

    // ================= Phase C: quantized W tile -> SMEM (transposed) ==============
    for (int i = tid; i < 64*NDIM; i += TPB) {
        const int nl = i >> 9, k = i & 511;
        sWt[k*WSTRIDE + nl] = rintf(W[(size_t)(mi*64 + nl)*NDIM + k] / scW) * scW;
    }
    gbar(&g_gcnt, &g_ggen, GRID);
    if (cta == 0 && tid == 0) { g_maxW = 0u; g_maxU = 0u; g_maxB = 0u; } // reset for replay

    // own Ux tile + z1 = relu(0.5*Ux)
    const int gout = nj*4096 + mi*512;
    for (int i = tid; i < 512; i += TPB) {
        const float v = __ldcg(&g_Ux[gout + i]);
        sUx[i] = v;
        __stcg(&g_zA[gout + i], fmaxf(0.5f * v, 0.f));
    }
    float* gz_cur = g_zA;
    float* gz_nxt = g_zB;
    gbar(&g_cnt[nj], &g_gen[nj], MT);

    // ================= Main loop: 39 iterations ====================================
    const int wid  = tid >> 5;              // K-split 0..7 (64 k each)
    const int lane = tid & 31;
    const int nb   = (lane >> 2) << 3;      // 8-row group
    const int bp   = (lane & 3) << 1;       // col pair
    const float* sWb = sWt + wid*64*WSTRIDE + nb;
    const int row  = tid >> 2;              // combine mapping
    const int cp   = (tid & 3) << 1;
    const int oidx = row*8 + cp;
    const int gz   = (mi*64 + row)*8 + cp;

    int cur = 0;
    for (int it = 1; it < ITERS; ++it) {
        float* szc = sZ + cur*4096;
        // warp-local staging of this warp's k-slice (no CTA barrier needed)
        {
            const float4* gsrc = (const float4*)(gz_cur + nj*4096 + wid*512);
            float4* sdst = (float4*)(szc + wid*512);
            #pragma unroll
            for (int j = 0; j < 4; ++j)
                sdst[lane + j*32] = __ldcg(gsrc + lane + j*32);
            __syncwarp();
        }

        const float* zr = szc + wid*512 + bp;
        ull a0=0,a1=0,a2=0,a3=0,a4=0,a5=0,a6=0,a7=0;
        #pragma unroll 8
        for (int k = 0; k < 64; ++k) {
            ulonglong2 wa = *(const ulonglong2*)(sWb + k*WSTRIDE);
            ulonglong2 wb = *(const ulonglong2*)(sWb + k*WSTRIDE + 4);
            float2 zz = *(const float2*)(zr + k*8);
            ull z0 = pk2(zz.x), z1 = pk2(zz.y);
            fma2(a0, wa.x, z0); fma2(a1, wa.x, z1);
            fma2(a2, wa.y, z0); fma2(a3, wa.y, z1);
            fma2(a4, wb.x, z0); fma2(a5, wb.x, z1);
            fma2(a6, wb.y, z0); fma2(a7, wb.y, z1);
        }
        {
            float* rp = sRed + wid*512 + nb*8 + bp;
            float x0, x1;
            upk2(a0,x0,x1); rp[0]  = x0; rp[8]  = x1;
            upk2(a1,x0,x1); rp[1]  = x0; rp[9]  = x1;
            upk2(a2,x0,x1); rp[16] = x0; rp[24] = x1;
            upk2(a3,x0,x1); rp[17] = x0; rp[25] = x1;
            upk2(a4,x0,x1); rp[32] = x0; rp[40] = x1;
            upk2(a5,x0,x1); rp[33] = x0; rp[41] = x1;
            upk2(a6,x0,x1); rp[48] = x0; rp[56] = x1;
            upk2(a7,x0,x1); rp[49] = x0; rp[57] = x1;
        }
        __syncthreads();
        {
            const float* rq = sRed + oidx;
            ull s = *(const ull*)(rq);
            #pragma unroll
            for (int q = 1; q < 8; ++q) s = add2(s, *(const ull*)(rq + q*512));
            ull uxv = *(const ull*)(sUx + oidx);
            float s0, s1, z0, z1, u0, u1;
            upk2(add2(s, uxv), s0, s1);
            upk2(*(const ull*)(szc + gz), z0, z1);
            u0 = fmaf(0.5f, z0, 0.5f * s0);
            u1 = fmaf(0.5f, z1, 0.5f * s1);
            __stcg((ull*)(gz_nxt + nj*4096 + gz), pk2b(fmaxf(u0, 0.f), fmaxf(u1, 0.f)));
        }
        { float* t = gz_cur; gz_cur = gz_nxt; gz_nxt = t; }
        cur ^= 1;
        gbar(&g_cnt[nj], &g_gen[nj], MT);
    }

    // ================= Classifier (row-tile 0 CTA of each group) ====================
    if (mi == 0 && tid < 8*CDIM) {
        const int bl = tid / CDIM, c = tid - bl*CDIM;
        const float* zp = gz_cur + nj*4096 + bl;
        const float* wc = Wc + c*NDIM;
        float acc = bcv[c];
        #pragma unroll 8
        for (int n = 0; n < NDIM; ++n)
            acc = fmaf(__ldcg(zp + n*8), wc[n], acc);
        out[(nj*8 + bl)*CDIM + c] = acc;
    }
}

extern "C" void kernel_launch(void* const* d_in, const int* in_sizes, int n_in,
                              void* d_out, int out_size) {
    (void)in_sizes; (void)n_in; (void)out_size;
    cudaFuncSetAttribute(mondeq_kernel, cudaFuncAttributeMaxDynamicSharedMemorySize, SMEM_BYTES);
    mondeq_kernel<<<GRID, TPB, SMEM_BYTES>>>(
        (const float*)d_in[0],   // W  (512,512)
        (const float*)d_in[1],   // U  (512,784)
        (const float*)d_in[2],   // b  (512)
        (const float*)d_in[3],   // x  (128,784)
        (const float*)d_in[4],   // Wc (10,512)
        (const float*)d_in[5],   // bc (10)
        (float*)d_out);          // logits (128,10)
}

// round 5
// speedup vs baseline: 1.6325x; 1.0946x over previous
#include <cuda_runtime.h>
#include <math.h>

typedef unsigned long long ull;

#define NDIM 512
#define DDIM 784
#define CDIM 10
#define ITERS 40
#define QMAX 127.0f

#define MT 8          // row tiles (64 rows each)
#define NT 16         // column groups (8 cols each)
#define GRID (MT*NT)  // 128 CTAs
#define TPB 512
#define WSTRIDE 68    // padded floats per k-row of sWt

// shared layout (float offsets)
#define S_WT   0          // 512*68 = 34816
#define S_Z    34816      // 2 x 4096 (double-buffered staged z, indexed k*8+col)
#define S_RED  43008      // 8 splits * 640 (64 rows * stride 10)
#define S_UX   48128      // 512
#define SMEM_FLOATS 48640
#define SMEM_BYTES (SMEM_FLOATS*4)

// ---- device globals (scratch) ----
__device__ float g_Ux[NDIM*128];
__device__ float g_zA[NDIM*128];
__device__ float g_zB[NDIM*128];
__device__ unsigned g_maxW, g_maxU, g_maxB;
__device__ unsigned g_gcnt, g_ggen;              // full-grid barrier
__device__ unsigned g_cnt[NT*8], g_gen[NT*8];    // per-group barriers (32B spaced)

// -------- full release/acquire barrier --------
__device__ __forceinline__ void gbar(unsigned* cnt, unsigned* gen, unsigned expected) {
    __syncthreads();
    if (threadIdx.x == 0) {
        unsigned snap, t;
        asm volatile("ld.acquire.gpu.global.u32 %0, [%1];" : "=r"(snap) : "l"(gen) : "memory");
        asm volatile("atom.acq_rel.gpu.global.add.u32 %0, [%1], %2;"
                     : "=r"(t) : "l"(cnt), "r"(1u) : "memory");
        if (t == expected - 1u) {
            asm volatile("st.relaxed.gpu.global.u32 [%0], %1;" :: "l"(cnt), "r"(0u) : "memory");
            asm volatile("red.release.gpu.global.add.u32 [%0], %1;" :: "l"(gen), "r"(1u) : "memory");
        } else {
            unsigned g;
            do {
                asm volatile("ld.acquire.gpu.global.u32 %0, [%1];" : "=r"(g) : "l"(gen) : "memory");
            } while (g == snap);
        }
    }
    __syncthreads();
}

// -------- f32x2 helpers --------
__device__ __forceinline__ ull pk2(float x){
    ull d; asm("mov.b64 %0, {%1,%1};" : "=l"(d) : "r"(__float_as_uint(x))); return d;
}
__device__ __forceinline__ ull pk2b(float x, float y){
    ull d; asm("mov.b64 %0, {%1,%2};" : "=l"(d) : "r"(__float_as_uint(x)), "r"(__float_as_uint(y))); return d;
}
__device__ __forceinline__ void upk2(ull v, float& x, float& y){
    unsigned a, b; asm("mov.b64 {%0,%1}, %2;" : "=r"(a), "=r"(b) : "l"(v));
    x = __uint_as_float(a); y = __uint_as_float(b);
}
__device__ __forceinline__ void fma2(ull& d, ull a, ull b){
    asm("fma.rn.f32x2 %0, %1, %2, %3;" : "=l"(d) : "l"(a), "l"(b), "l"(d));
}
__device__ __forceinline__ ull add2(ull a, ull b){
    ull d; asm("add.rn.f32x2 %0, %1, %2;" : "=l"(d) : "l"(a), "l"(b)); return d;
}
__device__ __forceinline__ float warpmax(float v){
    #pragma unroll
    for (int o = 16; o; o >>= 1) v = fmaxf(v, __shfl_xor_sync(0xffffffffu, v, o));
    return v;
}

extern "C" __global__ void __launch_bounds__(TPB, 1)
mondeq_kernel(const float* __restrict__ W, const float* __restrict__ U,
              const float* __restrict__ bvec, const float* __restrict__ x,
              const float* __restrict__ Wc, const float* __restrict__ bcv,
              float* __restrict__ out)
{
    extern __shared__ float sm[];
    float* sWt  = sm + S_WT;
    float* sZ   = sm + S_Z;
    float* sRed = sm + S_RED;
    float* sUx  = sm + S_UX;

    const int tid = threadIdx.x;
    const int cta = blockIdx.x;
    const int mi  = cta & (MT - 1);   // row tile 0..7
    const int nj  = cta >> 3;         // column group 0..15
    unsigned* bcnt = &g_cnt[nj*8];
    unsigned* bgen = &g_gen[nj*8];

    // ================= Phase A: per-tensor max|.| =================
    {
        float lw = 0.f, lu = 0.f, lb = 0.f;
        const int gid = cta * TPB + tid;
        for (int i = gid; i < NDIM*NDIM; i += GRID*TPB) lw = fmaxf(lw, fabsf(W[i]));
        for (int i = gid; i < NDIM*DDIM; i += GRID*TPB) lu = fmaxf(lu, fabsf(U[i]));
        if (gid < NDIM) lb = fabsf(bvec[gid]);
        lw = warpmax(lw); lu = warpmax(lu); lb = warpmax(lb);
        const int wd = tid >> 5, lane = tid & 31;
        if (lane == 0) { sm[wd] = lw; sm[16 + wd] = lu; sm[32 + wd] = lb; }
        __syncthreads();
        if (tid == 0) {
            float mw = 0.f, mu = 0.f, mb = 0.f;
            #pragma unroll
            for (int i = 0; i < 16; ++i) {
                mw = fmaxf(mw, sm[i]); mu = fmaxf(mu, sm[16+i]); mb = fmaxf(mb, sm[32+i]);
            }
            atomicMax(&g_maxW, __float_as_uint(mw));
            atomicMax(&g_maxU, __float_as_uint(mu));
            atomicMax(&g_maxB, __float_as_uint(mb));
        }
    }
    gbar(&g_gcnt, &g_ggen, GRID);

    const float scW = __uint_as_float(__ldcg(&g_maxW)) / QMAX;
    const float scU = __uint_as_float(__ldcg(&g_maxU)) / QMAX;
    const float scB = __uint_as_float(__ldcg(&g_maxB)) / QMAX;

    // ================= Phase B: Ux = Uq @ x^T + bq  (one dot per thread) ==========
    {
        float* xs = sm;            // [112][130] k-major padded
        float* us = sm + 14560;    // 4 x 112
        const int n0   = cta * 4;
        const int rr   = tid >> 7;      // U row 0..3
        const int bcol = tid & 127;     // batch col
        float acc = 0.f;
        for (int ch = 0; ch < 7; ++ch) {
            const int k0 = ch * 112;
            __syncthreads();
            for (int i = tid; i < 128*112; i += TPB) {
                const int bb = i / 112, kk = i - bb*112;
                xs[kk*130 + bb] = x[bb*DDIM + k0 + kk];
            }
            if (tid < 448) {
                const int r2 = tid / 112, kk = tid - r2*112;
                us[r2*112 + kk] = rintf(U[(n0+r2)*DDIM + k0 + kk] / scU) * scU;
            }
            __syncthreads();
            const float* up = us + rr*112;
            #pragma unroll 4
            for (int kk = 0; kk < 112; ++kk)
                acc = fmaf(up[kk], xs[kk*130 + bcol], acc);
        }
        const float bq = rintf(bvec[n0 + rr] / scB) * scB;
        __stcg(&g_Ux[(bcol>>3)*4096 + (n0+rr)*8 + (bcol&7)], acc + bq);
        __syncthreads();   // xs reads done before sWt overwrite
    }

    // ================= Phase C: quantized W tile -> SMEM (transposed) =============
    for (int i = tid; i < 64*NDIM; i += TPB) {
        const int nl = i >> 9, k = i & 511;
        sWt[k*WSTRIDE + nl] = rintf(W[(size_t)(mi*64 + nl)*NDIM + k] / scW) * scW;
    }
    gbar(&g_gcnt, &g_ggen, GRID);
    if (cta == 0 && tid == 0) { g_maxW = 0u; g_maxU = 0u; g_maxB = 0u; } // replay reset

    // own Ux tile + z1 = relu(0.5*Ux), staged locally + published globally
    const int gout = nj*4096 + mi*512;
    for (int i = tid; i < 512; i += TPB) {
        const float v = __ldcg(&g_Ux[gout + i]);
        sUx[i] = v;
        const float z1 = fmaxf(0.5f * v, 0.f);
        sZ[mi*512 + i] = z1;                 // own slice into buffer 0
        __stcg(&g_zA[gout + i], z1);
    }
    float* gz_cur = g_zA;
    float* gz_nxt = g_zB;
    gbar(&g_gcnt, &g_ggen, GRID);            // z1 visible everywhere

    // ================= Main loop: 39 iterations (z2..z40) ==========================
    const int wid  = tid >> 5;
    const int lane = tid & 31;
    const int ksp  = wid >> 1;                    // k-split 0..7
    const int rh   = wid & 1;                     // row half
    const int nb   = rh*32 + ((lane >> 2) << 2);  // 4-row group
    const int bp   = (lane & 3) << 1;             // col pair
    // combine mapping (tid < 256)
    const int row  = tid >> 2;
    const int cp   = (tid & 3) << 1;

    int cur = 0;
    for (int it = 2; it <= ITERS; ++it) {
        float* szc = sZ + cur*4096;
        // ---- arrive (non-blocking): my z_{it-1} stores are visible ----
        __syncthreads();
        unsigned bsnap = 0u;
        if (tid == 0) {
            unsigned t;
            asm volatile("ld.acquire.gpu.global.u32 %0, [%1];" : "=r"(bsnap) : "l"(bgen) : "memory");
            asm volatile("atom.acq_rel.gpu.global.add.u32 %0, [%1], %2;"
                         : "=r"(t) : "l"(bcnt), "r"(1u) : "memory");
            if (t == MT - 1u) {
                asm volatile("st.relaxed.gpu.global.u32 [%0], %1;" :: "l"(bcnt), "r"(0u) : "memory");
                asm volatile("red.release.gpu.global.add.u32 [%0], %1;" :: "l"(bgen), "r"(1u) : "memory");
            }
        }

        // ---- own-tile GEMM (k in own range; z staged locally last iter) ----
        ull a0=0, a1=0, a2=0, a3=0;
        {
            const float* wp = sWt + (mi*64 + ksp*8)*WSTRIDE + nb;
            const float* zp = szc + (mi*64 + ksp*8)*8 + bp;
            #pragma unroll
            for (int j = 0; j < 8; ++j) {
                ulonglong2 wa = *(const ulonglong2*)(wp + j*WSTRIDE);
                float2 zz = *(const float2*)(zp + j*8);
                ull z0 = pk2(zz.x), z1 = pk2(zz.y);
                fma2(a0, wa.x, z0); fma2(a1, wa.x, z1);
                fma2(a2, wa.y, z0); fma2(a3, wa.y, z1);
            }
        }

        // ---- wait: everyone's z_{it-1} visible ----
        if (tid == 0) {
            unsigned g;
            do {
                asm volatile("ld.acquire.gpu.global.u32 %0, [%1];" : "=r"(g) : "l"(bgen) : "memory");
            } while (g == bsnap);
        }
        __syncthreads();

        // ---- stage the 7 other tiles ----
        {
            const float4* gsrc = (const float4*)(gz_cur + nj*4096);
            float4* sdst = (float4*)szc;
            #pragma unroll
            for (int i2 = 0; i2 < 2; ++i2) {
                const int idx = tid + i2*TPB;
                if ((idx >> 7) != mi) sdst[idx] = __ldcg(gsrc + idx);
            }
        }
        __syncthreads();

        // ---- GEMM over remaining tiles ----
        #pragma unroll
        for (int t = 0; t < 8; ++t) {
            if (t == mi) continue;
            const float* wp = sWt + (t*64 + ksp*8)*WSTRIDE + nb;
            const float* zp = szc + (t*64 + ksp*8)*8 + bp;
            #pragma unroll
            for (int j = 0; j < 8; ++j) {
                ulonglong2 wa = *(const ulonglong2*)(wp + j*WSTRIDE);
                float2 zz = *(const float2*)(zp + j*8);
                ull z0 = pk2(zz.x), z1 = pk2(zz.y);
                fma2(a0, wa.x, z0); fma2(a1, wa.x, z1);
                fma2(a2, wa.y, z0); fma2(a3, wa.y, z1);
            }
        }

        // ---- partials to sRed (padded stride 10) ----
        {
            float* rp = sRed + ksp*640 + nb*10 + bp;
            float x0, x1;
            upk2(a0, x0, x1); rp[0]  = x0; rp[10] = x1;
            upk2(a1, x0, x1); rp[1]  = x0; rp[11] = x1;
            upk2(a2, x0, x1); rp[20] = x0; rp[30] = x1;
            upk2(a3, x0, x1); rp[21] = x0; rp[31] = x1;
        }
        __syncthreads();

        // ---- combine + relu + publish (threads 0..255) ----
        if (tid < 256) {
            const float* rq = sRed + row*10 + cp;
            ull s = *(const ull*)rq;
            #pragma unroll
            for (int q = 1; q < 8; ++q) s = add2(s, *(const ull*)(rq + q*640));
            s = add2(s, *(const ull*)(sUx + row*8 + cp));
            float s0, s1, z0, z1;
            upk2(s, s0, s1);
            upk2(*(const ull*)(szc + mi*512 + row*8 + cp), z0, z1);
            const float u0 = fmaf(0.5f, z0, 0.5f * s0);
            const float u1 = fmaf(0.5f, z1, 0.5f * s1);
            const ull zn = pk2b(fmaxf(u0, 0.f), fmaxf(u1, 0.f));
            *(ull*)(sZ + (cur^1)*4096 + mi*512 + row*8 + cp) = zn;      // local stage
            __stcg((ull*)(gz_nxt + nj*4096 + mi*512 + row*8 + cp), zn); // publish
        }
        { float* t = gz_cur; gz_cur = gz_nxt; gz_nxt = t; }
        cur ^= 1;
    }

    // final sync: all z40 published
    gbar(bcnt, bgen, MT);

    // ================= Classifier (row-tile 0 CTA of each group) ====================
    if (mi == 0 && tid < 8*CDIM) {
        const int bl = tid / CDIM, c = tid - bl*CDIM;
        const float* zp = gz_cur + nj*4096 + bl;
        const float* wc = Wc + c*NDIM;
        float acc = bcv[c];
        #pragma unroll 8
        for (int n = 0; n < NDIM; ++n)
            acc = fmaf(__ldcg(zp + n*8), wc[n], acc);
        out[(nj*8 + bl)*CDIM + c] = acc;
    }
}

extern "C" void kernel_launch(void* const* d_in, const int* in_sizes, int n_in,
                              void* d_out, int out_size) {
    (void)in_sizes; (void)n_in; (void)out_size;
    cudaFuncSetAttribute(mondeq_kernel, cudaFuncAttributeMaxDynamicSharedMemorySize, SMEM_BYTES);
    mondeq_kernel<<<GRID, TPB, SMEM_BYTES>>>(
        (const float*)d_in[0],   // W  (512,512)
        (const float*)d_in[1],   // U  (512,784)
        (const float*)d_in[2],   // b  (512)
        (const float*)d_in[3],   // x  (128,784)
        (const float*)d_in[4],   // Wc (10,512)
        (const float*)d_in[5],   // bc (10)
        (float*)d_out);          // logits (128,10)
}